// round 7
// baseline (speedup 1.0000x reference)
#include <cuda_runtime.h>

// DynamicFilterLayer2D: out[b,c,h,w] = sum_{i,j in 3x3} xpad[b,c,h+i,w+j] * f[b,c,i*3+j,h,w]
// B=8, C=32, H=256, W=256, K=3, zero pad 1.
// R5: R4's 4x4-patch layout (lowest traffic: 693MB, x vertical reuse in registers,
// 512B/instr warp coalescing) but with DEFAULT caching. R1/R3/R4 showed the
// __ldcs/__stcs hints reduce achieved DRAM BW (7048 -> 6618 GB/s) and exactly cancel
// their traffic savings. This isolates: low traffic + default-cache efficiency.

static constexpr int B = 8;
static constexpr int C = 32;
static constexpr int H = 256;
static constexpr int W = 256;
static constexpr int HW = H * W;
static constexpr int W4 = W / 4;   // 64
static constexpr int H4 = H / 4;   // 64

__global__ __launch_bounds__(256)
void dynamic_filter_kernel(const float* __restrict__ x,
                           const float* __restrict__ f,
                           float* __restrict__ out)
{
    int tid = blockIdx.x * blockDim.x + threadIdx.x;
    // total threads = B*C*H4*W4 = 1,048,576
    int w4 = tid & (W4 - 1);
    int t  = tid >> 6;
    int h4 = t & (H4 - 1);
    int bc = t >> 6;

    const int w0 = w4 * 4;
    const int h0 = h4 * 4;
    const long xbase = (long)bc * HW;
    const long fbase = (long)bc * 9 * HW;

    float acc[4][4];
    #pragma unroll
    for (int r = 0; r < 4; r++)
        #pragma unroll
        for (int k = 0; k < 4; k++) acc[r][k] = 0.f;

    // x rows needed: h0-1 .. h0+4. Row s contributes to output rows r = s-1, s, s+1
    // (within [0,3] of the patch) via tap i = s - r + 1.
    #pragma unroll
    for (int s = -1; s <= 4; s++) {
        const int hr = h0 + s;
        if (hr < 0 || hr >= H) continue;

        const float* xrow = x + xbase + (long)hr * W;
        const float4 cen = *reinterpret_cast<const float4*>(xrow + w0);
        float v[6];
        v[0] = (w0 > 0)     ? __ldg(xrow + w0 - 1) : 0.f;
        v[1] = cen.x; v[2] = cen.y; v[3] = cen.z; v[4] = cen.w;
        v[5] = (w0 + 4 < W) ? __ldg(xrow + w0 + 4) : 0.f;

        #pragma unroll
        for (int r = 0; r < 4; r++) {           // output row within patch
            const int i = s - r + 1;            // vertical tap
            if (i < 0 || i > 2) continue;       // compile-time prune
            const float* fp = f + fbase + (long)(i * 3) * HW + (long)(h0 + r) * W + w0;
            #pragma unroll
            for (int j = 0; j < 3; j++) {
                const float4 fv = *reinterpret_cast<const float4*>(fp + (long)j * HW);
                acc[r][0] = fmaf(fv.x, v[0 + j], acc[r][0]);
                acc[r][1] = fmaf(fv.y, v[1 + j], acc[r][1]);
                acc[r][2] = fmaf(fv.z, v[2 + j], acc[r][2]);
                acc[r][3] = fmaf(fv.w, v[3 + j], acc[r][3]);
            }
        }
    }

    #pragma unroll
    for (int r = 0; r < 4; r++) {
        *reinterpret_cast<float4*>(out + xbase + (long)(h0 + r) * W + w0) =
            make_float4(acc[r][0], acc[r][1], acc[r][2], acc[r][3]);
    }
}

extern "C" void kernel_launch(void* const* d_in, const int* in_sizes, int n_in,
                              void* d_out, int out_size)
{
    const float* x = (const float*)d_in[0];
    const float* f = (const float*)d_in[1];
    float* out = (float*)d_out;

    const int total = B * C * H4 * W4;   // 1,048,576 threads
    const int threads = 256;
    const int blocks = total / threads;  // 4096
    dynamic_filter_kernel<<<blocks, threads>>>(x, f, out);
}

// round 8
// speedup vs baseline: 1.0199x; 1.0199x over previous
#include <cuda_runtime.h>

// DynamicFilterLayer2D: out[b,c,h,w] = sum_{i,j in 3x3} xpad[b,c,h+i,w+j] * f[b,c,i*3+j,h,w]
// B=8, C=32, H=256, W=256, K=3, zero pad 1.
// R6: R1 layout (stride-4 in w, 512B warp-contiguous per instruction, default cache —
// the proven 7.05 TB/s config) but each thread handles TWO independent 4-px groups at
// rows h and h+128. Doubles per-warp MLP without touching coalescing; thread count
// only halves (2.1M). Tests whether deeper per-warp memory parallelism lifts achieved
// HBM BW past 88%.

static constexpr int B = 8;
static constexpr int C = 32;
static constexpr int H = 256;
static constexpr int W = 256;
static constexpr int HW = H * W;
static constexpr int W4 = W / 4;   // 64
static constexpr int H2 = H / 2;   // 128

__global__ __launch_bounds__(256)
void dynamic_filter_kernel(const float* __restrict__ x,
                           const float* __restrict__ f,
                           float* __restrict__ out)
{
    int tid = blockIdx.x * blockDim.x + threadIdx.x;
    // total threads = B*C*H2*W4 = 2,097,152
    int w4 = tid & (W4 - 1);
    int t  = tid >> 6;
    int h  = t & (H2 - 1);     // 0..127
    int bc = t >> 7;           // 0..255

    const int w0 = w4 * 4;
    const long xbase = (long)bc * HW;
    const long fbase = (long)bc * 9 * HW;

    float4 acc[2];
    acc[0] = make_float4(0.f, 0.f, 0.f, 0.f);
    acc[1] = make_float4(0.f, 0.f, 0.f, 0.f);

    #pragma unroll
    for (int i = 0; i < 3; i++) {
        // x row loads for both jobs (independent -> batched by compiler for MLP)
        float v[2][6];
        #pragma unroll
        for (int m = 0; m < 2; m++) {
            const int hr = h + m * 128 + i - 1;
            if (hr < 0 || hr >= H) {
                v[m][0] = v[m][1] = v[m][2] = v[m][3] = v[m][4] = v[m][5] = 0.f;
            } else {
                const float* xrow = x + xbase + (long)hr * W;
                const float4 cen = *reinterpret_cast<const float4*>(xrow + w0);
                v[m][0] = (w0 > 0)     ? __ldg(xrow + w0 - 1) : 0.f;
                v[m][1] = cen.x; v[m][2] = cen.y; v[m][3] = cen.z; v[m][4] = cen.w;
                v[m][5] = (w0 + 4 < W) ? __ldg(xrow + w0 + 4) : 0.f;
            }
        }

        #pragma unroll
        for (int j = 0; j < 3; j++) {
            #pragma unroll
            for (int m = 0; m < 2; m++) {
                const int hr = h + m * 128 + i - 1;
                if (hr < 0 || hr >= H) continue;   // filter tap multiplies zero-pad: skip
                const float* fp = f + fbase + (long)(i * 3 + j) * HW
                                + (long)(h + m * 128) * W + w0;
                const float4 fv = *reinterpret_cast<const float4*>(fp);
                acc[m].x = fmaf(fv.x, v[m][0 + j], acc[m].x);
                acc[m].y = fmaf(fv.y, v[m][1 + j], acc[m].y);
                acc[m].z = fmaf(fv.z, v[m][2 + j], acc[m].z);
                acc[m].w = fmaf(fv.w, v[m][3 + j], acc[m].w);
            }
        }
    }

    #pragma unroll
    for (int m = 0; m < 2; m++) {
        *reinterpret_cast<float4*>(out + xbase + (long)(h + m * 128) * W + w0) = acc[m];
    }
}

extern "C" void kernel_launch(void* const* d_in, const int* in_sizes, int n_in,
                              void* d_out, int out_size)
{
    const float* x = (const float*)d_in[0];
    const float* f = (const float*)d_in[1];
    float* out = (float*)d_out;

    const int total = B * C * H2 * W4;   // 2,097,152 threads
    const int threads = 256;
    const int blocks = total / threads;  // 8192
    dynamic_filter_kernel<<<blocks, threads>>>(x, f, out);
}

// round 10
// speedup vs baseline: 1.0592x; 1.0386x over previous
#include <cuda_runtime.h>

// DynamicFilterLayer2D: out[b,c,h,w] = sum_{i,j in 3x3} xpad[b,c,h+i,w+j] * f[b,c,i*3+j,h,w]
// B=8, C=32, H=256, W=256, K=3, zero pad 1.
//
// FINAL (= R1; R8 was an infra failure, resubmitting unchanged). Search summary:
//  - Traffic floor 738MB; this kernel moves ~730MB at 7048 GB/s (88% of 8TB/s spec,
//    ~102% of the measured ~6300 B/cyc LTS path ceiling) -> 103.6us kernel time.
//  - R2 (8px/thread): broke 512B/instr warp coalescing -> 130us. REJECTED.
//  - R3 (__ldcs/__stcs): -30MB traffic but -4% achieved BW -> time-neutral. REJECTED.
//  - R4/R5/R6 (patch/dual-row tiling): regs 42-44 -> occ 89%->57% -> BW -5% -> slower.
//    Achieved HBM BW on sm_103a tracks resident-warp count, not per-warp MLP. REJECTED.
//  - Winning config: 32 regs, 89% occupancy, 4px/thread (float4), contiguous warp
//    segments, default caching.

static constexpr int B = 8;
static constexpr int C = 32;
static constexpr int H = 256;
static constexpr int W = 256;
static constexpr int HW = H * W;
static constexpr int W4 = W / 4;

__global__ __launch_bounds__(256)
void dynamic_filter_kernel(const float* __restrict__ x,
                           const float* __restrict__ f,
                           float* __restrict__ out)
{
    int tid = blockIdx.x * blockDim.x + threadIdx.x;
    // total threads = B*C*H*W4 = 4,194,304
    int w4 = tid & (W4 - 1);
    int t = tid >> 6;          // W4 = 64
    int h = t & (H - 1);
    int bc = t >> 8;           // H = 256

    const int w0 = w4 * 4;
    const long xbase = (long)bc * HW;
    const long fbase = (long)bc * 9 * HW;

    float4 acc = make_float4(0.f, 0.f, 0.f, 0.f);

    #pragma unroll
    for (int i = 0; i < 3; i++) {
        const int hr = h + i - 1;
        if (hr < 0 || hr >= H) continue;

        const float* xrow = x + xbase + (long)hr * W;
        const float4 cen = *reinterpret_cast<const float4*>(xrow + w0);
        const float xl = (w0 > 0)     ? __ldg(xrow + w0 - 1) : 0.f;
        const float xr = (w0 + 4 < W) ? __ldg(xrow + w0 + 4) : 0.f;

        const float v0 = xl, v1 = cen.x, v2 = cen.y, v3 = cen.z, v4 = cen.w, v5 = xr;

        const float* fp = f + fbase + (long)(i * 3) * HW + (long)h * W + w0;
        {
            const float4 fv = *reinterpret_cast<const float4*>(fp);            // j = 0
            acc.x = fmaf(fv.x, v0, acc.x);
            acc.y = fmaf(fv.y, v1, acc.y);
            acc.z = fmaf(fv.z, v2, acc.z);
            acc.w = fmaf(fv.w, v3, acc.w);
        }
        {
            const float4 fv = *reinterpret_cast<const float4*>(fp + HW);       // j = 1
            acc.x = fmaf(fv.x, v1, acc.x);
            acc.y = fmaf(fv.y, v2, acc.y);
            acc.z = fmaf(fv.z, v3, acc.z);
            acc.w = fmaf(fv.w, v4, acc.w);
        }
        {
            const float4 fv = *reinterpret_cast<const float4*>(fp + 2 * HW);   // j = 2
            acc.x = fmaf(fv.x, v2, acc.x);
            acc.y = fmaf(fv.y, v3, acc.y);
            acc.z = fmaf(fv.z, v4, acc.z);
            acc.w = fmaf(fv.w, v5, acc.w);
        }
    }

    *reinterpret_cast<float4*>(out + xbase + (long)h * W + w0) = acc;
}

extern "C" void kernel_launch(void* const* d_in, const int* in_sizes, int n_in,
                              void* d_out, int out_size)
{
    const float* x = (const float*)d_in[0];
    const float* f = (const float*)d_in[1];
    float* out = (float*)d_out;

    const int total = B * C * H * W4;   // 4,194,304 threads
    const int threads = 256;
    const int blocks = total / threads; // 16384
    dynamic_filter_kernel<<<blocks, threads>>>(x, f, out);
}